// round 2
// baseline (speedup 1.0000x reference)
#include <cuda_runtime.h>
#include <math.h>

#define D 128
static constexpr int MAXN = 51200;

// Scratch (no allocs allowed -> device globals)
__device__ float d_mj[MAXN * D];
__device__ float d_v [MAXN * D];

__device__ __forceinline__ float ssp(float x) {
    // shifted softplus: logaddexp(x,0) - log(2), numerically stable both tails
    return fmaxf(x, 0.0f) + log1pf(__expf(-fabsf(x))) - 0.69314718055994530942f;
}

// ---------------------------------------------------------------------------
// GEMM: out = post( preact(A) @ W + bias )
// A: [N,128], W: [128,128] row-major. Tile 128x128, BK=8, 256 thr, 8x8 micro.
// Used only for the two leading GEMMs (Wj, Wi) reading ssp(x) on the fly.
// ---------------------------------------------------------------------------
template<bool PRE, bool POST>
__global__ __launch_bounds__(256, 2)
void mm128_kernel(const float* __restrict__ A,
                  const float* __restrict__ W,
                  const float* __restrict__ bias,
                  float* __restrict__ out,
                  int N) {
    __shared__ float As[8][132];
    __shared__ float Bs[8][128];

    const int t    = threadIdx.x;
    const int row0 = blockIdx.x * 128;

    const int arow = t >> 1;
    const int acol = (t & 1) << 2;
    const int wrow = t >> 5;
    const int wcol = (t & 31) << 2;

    const int mrow = (t >> 4) << 3;
    const int ncol = (t & 15) << 3;

    float acc[8][8];
    #pragma unroll
    for (int i = 0; i < 8; i++)
        #pragma unroll
        for (int j = 0; j < 8; j++)
            acc[i][j] = 0.0f;

    const int agr = row0 + arow;
    const bool avalid = (agr < N);

    for (int kc = 0; kc < 128; kc += 8) {
        float4 av;
        if (avalid) av = *reinterpret_cast<const float4*>(A + (size_t)agr * D + kc + acol);
        else        av = make_float4(0.f, 0.f, 0.f, 0.f);
        if (PRE) { av.x = ssp(av.x); av.y = ssp(av.y); av.z = ssp(av.z); av.w = ssp(av.w); }
        As[acol + 0][arow] = av.x;
        As[acol + 1][arow] = av.y;
        As[acol + 2][arow] = av.z;
        As[acol + 3][arow] = av.w;

        float4 wv = *reinterpret_cast<const float4*>(W + (size_t)(kc + wrow) * D + wcol);
        *reinterpret_cast<float4*>(&Bs[wrow][wcol]) = wv;

        __syncthreads();

        #pragma unroll
        for (int kk = 0; kk < 8; kk++) {
            float a[8], b[8];
            #pragma unroll
            for (int i = 0; i < 8; i++) a[i] = As[kk][mrow + i];
            #pragma unroll
            for (int j = 0; j < 8; j++) b[j] = Bs[kk][ncol + j];
            #pragma unroll
            for (int i = 0; i < 8; i++)
                #pragma unroll
                for (int j = 0; j < 8; j++)
                    acc[i][j] = fmaf(a[i], b[j], acc[i][j]);
        }
        __syncthreads();
    }

    float bv[8];
    #pragma unroll
    for (int j = 0; j < 8; j++) bv[j] = bias[ncol + j];

    #pragma unroll
    for (int i = 0; i < 8; i++) {
        int r = row0 + mrow + i;
        if (r < N) {
            size_t off = (size_t)r * D + ncol;
            #pragma unroll
            for (int j = 0; j < 8; j++) {
                float val = acc[i][j] + bv[j];
                if (POST) val = ssp(val);
                out[off + j] = val;
            }
        }
    }
}

// ---------------------------------------------------------------------------
// Edge kernel: gate = g_ij[e,:] @ Wg; v[idx_i[e],:] += gate * mj[idx_j[e],:]
// One warp per edge; lane handles 4 consecutive d; ONE red.global.v4 per lane.
// ---------------------------------------------------------------------------
__global__ __launch_bounds__(256)
void edge_kernel(const float* __restrict__ g,
                 const float* __restrict__ Wg,
                 const int* __restrict__ idx_i,
                 const int* __restrict__ idx_j,
                 const float* __restrict__ mj,
                 float* __restrict__ v,
                 int E, int R) {
    __shared__ float4 Wgs[32 * 32];  // up to R=32 rows x 128 cols
    for (int i = threadIdx.x; i < R * 32; i += blockDim.x)
        Wgs[i] = reinterpret_cast<const float4*>(Wg)[i];
    __syncthreads();

    const int lane   = threadIdx.x & 31;
    const int warp   = (blockIdx.x * blockDim.x + threadIdx.x) >> 5;
    const int nwarps = (gridDim.x * blockDim.x) >> 5;

    for (int e = warp; e < E; e += nwarps) {
        float gval = (lane < R) ? __ldg(g + (size_t)e * R + lane) : 0.0f;
        const int j = __ldg(idx_j + e);
        const int i = __ldg(idx_i + e);

        float4 acc = make_float4(0.f, 0.f, 0.f, 0.f);
        #pragma unroll 8
        for (int r = 0; r < R; r++) {
            float gr = __shfl_sync(0xffffffffu, gval, r);
            float4 w = Wgs[r * 32 + lane];
            acc.x = fmaf(gr, w.x, acc.x);
            acc.y = fmaf(gr, w.y, acc.y);
            acc.z = fmaf(gr, w.z, acc.z);
            acc.w = fmaf(gr, w.w, acc.w);
        }

        float4 m = reinterpret_cast<const float4*>(mj)[(size_t)j * 32 + lane];
        float* vp = v + (size_t)i * D + lane * 4;
        float vx = acc.x * m.x, vy = acc.y * m.y, vz = acc.z * m.z, vw = acc.w * m.w;
        asm volatile("red.global.add.v4.f32 [%0], {%1, %2, %3, %4};"
                     :: "l"(vp), "f"(vx), "f"(vy), "f"(vz), "f"(vw) : "memory");
    }
}

// ---------------------------------------------------------------------------
// Fused tail kernel: per 64-row tile, keep v (Vr) and ssp(v) (Av) in smem,
// run: n_int residuals -> Wf(+u*ssp(x)) -> n_atom residuals -> store h ->
//      n_out residuals -> store o = ssp(.)
// Layout: Av/Vr row-major [64][132]; Bs [16][128] streamed per 16-k chunk.
// 256 threads, micro-tile 4x8 (mrow=(t>>4)*4, ncol=(t&15)*8).
// ---------------------------------------------------------------------------
#define AV_S 132

__device__ __forceinline__ void gemm_tile(const float* __restrict__ W,
                                          const float* __restrict__ Av,
                                          float* __restrict__ Bs,
                                          int mrow, int ncol, int t,
                                          float acc[4][8]) {
    #pragma unroll
    for (int i = 0; i < 4; i++)
        #pragma unroll
        for (int j = 0; j < 8; j++) acc[i][j] = 0.0f;

    #pragma unroll
    for (int kc = 0; kc < 128; kc += 16) {
        // stage W chunk [16][128] into Bs (2 float4 per thread)
        const int lin0 = t, lin1 = 256 + t;
        float4 w0 = *reinterpret_cast<const float4*>(W + (size_t)(kc + (lin0 >> 5)) * D + ((lin0 & 31) << 2));
        float4 w1 = *reinterpret_cast<const float4*>(W + (size_t)(kc + (lin1 >> 5)) * D + ((lin1 & 31) << 2));
        __syncthreads();   // prev chunk fma done (and caller's Av writes visible below)
        *reinterpret_cast<float4*>(&Bs[(lin0 >> 5) * D + ((lin0 & 31) << 2)]) = w0;
        *reinterpret_cast<float4*>(&Bs[(lin1 >> 5) * D + ((lin1 & 31) << 2)]) = w1;
        __syncthreads();

        #pragma unroll
        for (int kk4 = 0; kk4 < 4; kk4++) {
            float4 a4[4];
            #pragma unroll
            for (int i = 0; i < 4; i++)
                a4[i] = *reinterpret_cast<const float4*>(&Av[(mrow + i) * AV_S + kc + (kk4 << 2)]);
            #pragma unroll
            for (int kin = 0; kin < 4; kin++) {
                float b[8];
                *reinterpret_cast<float4*>(b)     = *reinterpret_cast<const float4*>(&Bs[((kk4 << 2) + kin) * D + ncol]);
                *reinterpret_cast<float4*>(b + 4) = *reinterpret_cast<const float4*>(&Bs[((kk4 << 2) + kin) * D + ncol + 4]);
                #pragma unroll
                for (int i = 0; i < 4; i++) {
                    float av = reinterpret_cast<const float*>(&a4[i])[kin];
                    #pragma unroll
                    for (int j = 0; j < 8; j++)
                        acc[i][j] = fmaf(av, b[j], acc[i][j]);
                }
            }
        }
    }
    __syncthreads();   // all fma done: caller may overwrite Av
}

__device__ __forceinline__ void do_residual(const float* __restrict__ W,
                                            const float* __restrict__ b,
                                            float* __restrict__ Av,
                                            float* __restrict__ Vr,
                                            float* __restrict__ Bs,
                                            int mrow, int ncol, int t) {
    float acc[4][8];
    float bv[8];
    #pragma unroll
    for (int j = 0; j < 8; j++) bv[j] = __ldg(b + ncol + j);

    // t1 = ssp(v) @ W + b ; Av <- ssp(t1)
    gemm_tile(W, Av, Bs, mrow, ncol, t, acc);
    #pragma unroll
    for (int i = 0; i < 4; i++)
        #pragma unroll
        for (int j = 0; j < 8; j++)
            Av[(mrow + i) * AV_S + ncol + j] = ssp(acc[i][j] + bv[j]);
    // (gemm_tile's internal sync pair orders these writes before next fma)

    // v' = ssp(t1) @ W + b + v
    gemm_tile(W, Av, Bs, mrow, ncol, t, acc);
    #pragma unroll
    for (int i = 0; i < 4; i++)
        #pragma unroll
        for (int j = 0; j < 8; j++) {
            float val = acc[i][j] + bv[j] + Vr[(mrow + i) * AV_S + ncol + j];
            Vr[(mrow + i) * AV_S + ncol + j] = val;
            Av[(mrow + i) * AV_S + ncol + j] = ssp(val);
        }
}

__global__ __launch_bounds__(256, 2)
void tail_kernel(const float* __restrict__ v_in,
                 const float* __restrict__ x,
                 const float* __restrict__ u,
                 const float* __restrict__ rWint, const float* __restrict__ rbint, int n_int,
                 const float* __restrict__ Wf, const float* __restrict__ bf,
                 const float* __restrict__ rWatm, const float* __restrict__ rbatm, int n_atom,
                 const float* __restrict__ rWout, const float* __restrict__ rbout, int n_out,
                 float* __restrict__ h_out, float* __restrict__ o_out, int N) {
    extern __shared__ float sm[];
    float* Av = sm;                 // [64][AV_S]  ssp(current value)
    float* Vr = sm + 64 * AV_S;     // [64][AV_S]  current value
    float* Bs = sm + 128 * AV_S;    // [16][128]   weight chunk

    const int t    = threadIdx.x;
    const int row0 = blockIdx.x * 64;
    const int mrow = (t >> 4) << 2;
    const int ncol = (t & 15) << 3;

    // init: Vr = v tile, Av = ssp(v tile)
    {
        int r  = t >> 2;
        int gr = row0 + r;
        #pragma unroll
        for (int p = 0; p < 8; p++) {
            int c = ((t & 3) << 2) + (p << 4);
            float4 val;
            if (gr < N) val = *reinterpret_cast<const float4*>(v_in + (size_t)gr * D + c);
            else        val = make_float4(0.f, 0.f, 0.f, 0.f);
            *reinterpret_cast<float4*>(&Vr[r * AV_S + c]) = val;
            float4 s = make_float4(ssp(val.x), ssp(val.y), ssp(val.z), ssp(val.w));
            *reinterpret_cast<float4*>(&Av[r * AV_S + c]) = s;
        }
    }
    // (first gemm's internal sync orders init writes before fma reads)

    // interaction residual stack
    for (int k = 0; k < n_int; k++)
        do_residual(rWint + (size_t)k * D * D, rbint + (size_t)k * D, Av, Vr, Bs, mrow, ncol, t);

    // h = u*ssp(x) + ssp(v) @ Wf + bf
    {
        float acc[4][8];
        gemm_tile(Wf, Av, Bs, mrow, ncol, t, acc);
        float bv[8], uv[8];
        #pragma unroll
        for (int j = 0; j < 8; j++) { bv[j] = __ldg(bf + ncol + j); uv[j] = __ldg(u + ncol + j); }
        #pragma unroll
        for (int i = 0; i < 4; i++) {
            int gr = row0 + mrow + i;
            float xv[8];
            if (gr < N) {
                *reinterpret_cast<float4*>(xv)     = *reinterpret_cast<const float4*>(x + (size_t)gr * D + ncol);
                *reinterpret_cast<float4*>(xv + 4) = *reinterpret_cast<const float4*>(x + (size_t)gr * D + ncol + 4);
            } else {
                #pragma unroll
                for (int j = 0; j < 8; j++) xv[j] = 0.f;
            }
            #pragma unroll
            for (int j = 0; j < 8; j++) {
                float val = acc[i][j] + bv[j] + uv[j] * ssp(xv[j]);
                Vr[(mrow + i) * AV_S + ncol + j] = val;
                Av[(mrow + i) * AV_S + ncol + j] = ssp(val);
            }
        }
    }

    // atomic residual stack
    for (int k = 0; k < n_atom; k++)
        do_residual(rWatm + (size_t)k * D * D, rbatm + (size_t)k * D, Av, Vr, Bs, mrow, ncol, t);

    // store h (second half of d_out)
    #pragma unroll
    for (int i = 0; i < 4; i++) {
        int gr = row0 + mrow + i;
        if (gr < N) {
            *reinterpret_cast<float4*>(h_out + (size_t)gr * D + ncol) =
                *reinterpret_cast<const float4*>(&Vr[(mrow + i) * AV_S + ncol]);
            *reinterpret_cast<float4*>(h_out + (size_t)gr * D + ncol + 4) =
                *reinterpret_cast<const float4*>(&Vr[(mrow + i) * AV_S + ncol + 4]);
        }
    }

    // output residual stack
    for (int k = 0; k < n_out; k++)
        do_residual(rWout + (size_t)k * D * D, rbout + (size_t)k * D, Av, Vr, Bs, mrow, ncol, t);

    // store o = ssp(final)  (Av already holds it)
    #pragma unroll
    for (int i = 0; i < 4; i++) {
        int gr = row0 + mrow + i;
        if (gr < N) {
            *reinterpret_cast<float4*>(o_out + (size_t)gr * D + ncol) =
                *reinterpret_cast<const float4*>(&Av[(mrow + i) * AV_S + ncol]);
            *reinterpret_cast<float4*>(o_out + (size_t)gr * D + ncol + 4) =
                *reinterpret_cast<const float4*>(&Av[(mrow + i) * AV_S + ncol + 4]);
        }
    }
}

// ---------------------------------------------------------------------------
// Host-side dispatch
// ---------------------------------------------------------------------------
static constexpr int TAIL_SMEM = (128 * AV_S + 16 * 128) * 4;

extern "C" void kernel_launch(void* const* d_in, const int* in_sizes, int n_in,
                              void* d_out, int out_size) {
    const float* x     = (const float*)d_in[0];
    const float* g_ij  = (const float*)d_in[1];
    const float* Wf    = (const float*)d_in[2];
    const float* bf    = (const float*)d_in[3];
    const float* Wg    = (const float*)d_in[4];
    const float* Wj    = (const float*)d_in[5];
    const float* bj    = (const float*)d_in[6];
    const float* Wi    = (const float*)d_in[7];
    const float* bi    = (const float*)d_in[8];
    const float* u     = (const float*)d_in[9];
    const float* rWint = (const float*)d_in[10];
    const float* rbint = (const float*)d_in[11];
    const float* rWatm = (const float*)d_in[12];
    const float* rbatm = (const float*)d_in[13];
    const float* rWout = (const float*)d_in[14];
    const float* rbout = (const float*)d_in[15];
    const int*   idx_i = (const int*)d_in[16];
    const int*   idx_j = (const int*)d_in[17];

    const int N      = in_sizes[0] / D;
    const int E      = in_sizes[16];
    const int R      = in_sizes[4] / D;
    const int n_int  = in_sizes[11] / D;
    const int n_atom = in_sizes[13] / D;
    const int n_out  = in_sizes[15] / D;

    if (N > MAXN) return;

    float *mj, *v;
    cudaGetSymbolAddress((void**)&mj, d_mj);
    cudaGetSymbolAddress((void**)&v,  d_v);

    float* o_out = (float*)d_out;                 // o -> first N*D
    float* h_out = (float*)d_out + (size_t)N * D; // h -> second N*D

    cudaFuncSetAttribute(tail_kernel, cudaFuncAttributeMaxDynamicSharedMemorySize, TAIL_SMEM);

    dim3 grid128((N + 127) / 128), blk(256);

    // 1) mj = ssp(ssp(x) @ Wj + bj)   (node-level message transform)
    mm128_kernel<true, true><<<grid128, blk>>>(x, Wj, bj, mj, N);

    // 2) v = ssp(ssp(x) @ Wi + bi)
    mm128_kernel<true, true><<<grid128, blk>>>(x, Wi, bi, v, N);

    // 3) v += segment_sum( (g_ij @ Wg) * mj[idx_j], idx_i )  (vector red)
    edge_kernel<<<2048, 256>>>(g_ij, Wg, idx_i, idx_j, mj, v, E, R);

    // 4) fused row-local tail: residuals + Wf + atom/out stacks + stores
    tail_kernel<<<(N + 63) / 64, blk, TAIL_SMEM>>>(
        v, x, u,
        rWint, rbint, n_int,
        Wf, bf,
        rWatm, rbatm, n_atom,
        rWout, rbout, n_out,
        h_out, o_out, N);
}

// round 4
// speedup vs baseline: 2.2441x; 2.2441x over previous
#include <cuda_runtime.h>
#include <cuda_bf16.h>
#include <math.h>
#include <stdint.h>

#define D 128
static constexpr int MAXN = 51200;
static constexpr int MAXMATS = 16;

// ---------------------------------------------------------------------------
// Scratch (no allocs allowed -> device globals)
// ---------------------------------------------------------------------------
__device__ float d_mj[MAXN * D];
__device__ float d_v [MAXN * D];
// Pre-split, pre-permuted weight images. Per matrix: 16384 uint32 words:
//   words [0,8192)  = hi bf16x2 in B-fragment order
//   words [8192,..) = lo bf16x2 in B-fragment order
// Fragment order: word idx = ((nt*8 + kt)*32 + lane)*2 + ri
//   value = pack_bf16x2( W[k0][n], W[k0+1][n] )
//   n = nt*8 + lane/4 ; k0 = kt*16 + 2*(lane%4) + ri*8
__device__ uint32_t d_wimg[MAXMATS * 16384];

__device__ __forceinline__ float sspf(float x) {
    // shifted softplus: max(x,0) + log(1+exp(-|x|)) - log(2)
    return fmaxf(x, 0.0f) + __logf(1.0f + __expf(-fabsf(x))) - 0.69314718055994530942f;
}

// ---------------------------------------------------------------------------
// HMMA m16n8k16 bf16 (base PTX, works at compute_103)
// ---------------------------------------------------------------------------
__device__ __forceinline__ void mma_bf16(float* d, const uint32_t* a,
                                         uint32_t b0, uint32_t b1) {
    asm volatile(
        "mma.sync.aligned.m16n8k16.row.col.f32.bf16.bf16.f32 "
        "{%0,%1,%2,%3}, {%4,%5,%6,%7}, {%8,%9}, {%0,%1,%2,%3};"
        : "+f"(d[0]), "+f"(d[1]), "+f"(d[2]), "+f"(d[3])
        : "r"(a[0]), "r"(a[1]), "r"(a[2]), "r"(a[3]), "r"(b0), "r"(b1));
}

__device__ __forceinline__ void build_frag(float s0, float s1,
                                           uint32_t& hi, uint32_t& lo) {
    __nv_bfloat162 h2 = __floats2bfloat162_rn(s0, s1);
    float l0 = s0 - __bfloat162float(h2.x);
    float l1 = s1 - __bfloat162float(h2.y);
    __nv_bfloat162 l2 = __floats2bfloat162_rn(l0, l1);
    hi = *reinterpret_cast<uint32_t*>(&h2);
    lo = *reinterpret_cast<uint32_t*>(&l2);
}

// ---------------------------------------------------------------------------
// Weight precompute: split W (k-major [128][128]) into hi/lo bf16 images in
// B-fragment order (see layout comment above).
// ---------------------------------------------------------------------------
__global__ void wsplit_kernel(const float* __restrict__ Wj,
                              const float* __restrict__ Wi,
                              const float* __restrict__ Wf,
                              const float* __restrict__ rWint,
                              const float* __restrict__ rWatm,
                              const float* __restrict__ rWout,
                              int n_int, int n_atom, int n_out) {
    int m = blockIdx.x;
    const float* src;
    if (m == 0)                      src = Wj;
    else if (m == 1)                 src = Wi;
    else if (m == 2)                 src = Wf;
    else if (m < 3 + n_int)          src = rWint + (size_t)(m - 3) * D * D;
    else if (m < 3 + n_int + n_atom) src = rWatm + (size_t)(m - 3 - n_int) * D * D;
    else                             src = rWout + (size_t)(m - 3 - n_int - n_atom) * D * D;

    uint32_t* hi = d_wimg + (size_t)m * 16384;
    uint32_t* lo = hi + 8192;

    for (int idx = threadIdx.x; idx < 8192; idx += blockDim.x) {
        int ri = idx & 1;
        int l  = (idx >> 1) & 31;
        int f  = idx >> 6;            // 0..127 = nt*8 + kt
        int kt = f & 7, nt = f >> 3;
        int n  = nt * 8 + (l >> 2);
        int k0 = kt * 16 + 2 * (l & 3) + ri * 8;
        float w0 = src[k0 * D + n];
        float w1 = src[(k0 + 1) * D + n];
        uint32_t h, lw;
        build_frag(w0, w1, h, lw);
        hi[idx] = h;
        lo[idx] = lw;
    }
}

// ---------------------------------------------------------------------------
// Stage helpers: 256 threads (8 warps). Warp w owns rows row0+w*16 .. +15.
// Lane l: g = l/4 (row within 8), m4 = l%4 (col pair).
// acc[nt*4 + {0,1,2,3}] = out(row_lo, c0), (row_lo, c0+1), (row_hi, c0), (row_hi, c0+1)
//   with c0 = nt*8 + 2*m4, row_lo = base + g, row_hi = base + g + 8.
// A-fragments chain: a-frag kt regs = acc n-tiles (2kt, 2kt+1) repacked.
// ---------------------------------------------------------------------------
__device__ __forceinline__ void stage_load_w(uint32_t* wsm, float* bias_s,
                                             const uint32_t* img,
                                             const float* bias, int t) {
    __syncthreads();   // all warps done with previous stage's W
    const uint4* src = reinterpret_cast<const uint4*>(img);
    uint4* dst = reinterpret_cast<uint4*>(wsm);
    #pragma unroll
    for (int i = 0; i < 16; i++)
        dst[t + 256 * i] = src[t + 256 * i];
    if (t < 32)
        reinterpret_cast<float4*>(bias_s)[t] =
            reinterpret_cast<const float4*>(bias)[t];
    __syncthreads();
}

__device__ __forceinline__ void stage_mma(const uint32_t* wsm, int loff,
                                          const uint32_t* ahi, const uint32_t* alo,
                                          float* acc) {
    const char* base = reinterpret_cast<const char*>(wsm);
    #pragma unroll
    for (int kt = 0; kt < 8; kt++) {
        #pragma unroll
        for (int nt = 0; nt < 16; nt++) {
            uint2 bh = *reinterpret_cast<const uint2*>(base + (nt * 8 + kt) * 256 + loff);
            mma_bf16(acc + nt * 4, ahi + kt * 4, bh.x, bh.y);
            mma_bf16(acc + nt * 4, alo + kt * 4, bh.x, bh.y);
            uint2 bl = *reinterpret_cast<const uint2*>(base + 32768 + (nt * 8 + kt) * 256 + loff);
            mma_bf16(acc + nt * 4, ahi + kt * 4, bl.x, bl.y);
        }
    }
}

static constexpr int SMEM_WORDS = 16384 + 128 + 128;
static constexpr int SMEM_BYTES = SMEM_WORDS * 4;   // 66560

// ---------------------------------------------------------------------------
// Head kernel: A = ssp(x); mj = ssp(A@Wj + bj); v = ssp(A@Wi + bi)
// ---------------------------------------------------------------------------
__global__ void __launch_bounds__(256, 1)
tc_head_kernel(const float* __restrict__ x,
               const float* __restrict__ bj, const float* __restrict__ bi,
               float* __restrict__ mj, float* __restrict__ v, int N) {
    extern __shared__ uint32_t sm[];
    float* bias_s = reinterpret_cast<float*>(sm + 16384);

    const int t = threadIdx.x, w = t >> 5, l = t & 31;
    const int g = l >> 2, m4 = l & 3;
    const int loff = l * 8;
    const int row_lo = blockIdx.x * 128 + w * 16 + g;
    const int row_hi = row_lo + 8;
    const int cb = 2 * m4;

    uint32_t ahi[32], alo[32];
    #pragma unroll
    for (int nt = 0; nt < 16; nt++) {
        int c0 = nt * 8 + cb;
        float2 a = (row_lo < N) ? *reinterpret_cast<const float2*>(x + (size_t)row_lo * D + c0)
                                : make_float2(0.f, 0.f);
        float2 b = (row_hi < N) ? *reinterpret_cast<const float2*>(x + (size_t)row_hi * D + c0)
                                : make_float2(0.f, 0.f);
        int base = (nt >> 1) * 4 + (nt & 1) * 2;
        build_frag(sspf(a.x), sspf(a.y), ahi[base], alo[base]);
        build_frag(sspf(b.x), sspf(b.y), ahi[base + 1], alo[base + 1]);
    }

    for (int s = 0; s < 2; s++) {
        stage_load_w(sm, bias_s, d_wimg + (size_t)s * 16384, s ? bi : bj, t);
        float acc[64];
        #pragma unroll
        for (int i = 0; i < 64; i++) acc[i] = 0.0f;
        stage_mma(sm, loff, ahi, alo, acc);

        float* outp = s ? v : mj;
        #pragma unroll
        for (int nt = 0; nt < 16; nt++) {
            int c0 = nt * 8 + cb;
            float bv0 = bias_s[c0], bv1 = bias_s[c0 + 1];
            float s0 = sspf(acc[nt * 4 + 0] + bv0);
            float s1 = sspf(acc[nt * 4 + 1] + bv1);
            float s2 = sspf(acc[nt * 4 + 2] + bv0);
            float s3 = sspf(acc[nt * 4 + 3] + bv1);
            if (row_lo < N)
                *reinterpret_cast<float2*>(outp + (size_t)row_lo * D + c0) = make_float2(s0, s1);
            if (row_hi < N)
                *reinterpret_cast<float2*>(outp + (size_t)row_hi * D + c0) = make_float2(s2, s3);
        }
    }
}

// ---------------------------------------------------------------------------
// Tail kernel: fully register-chained stage loop.
// Modes: 0 RES1 (A<-ssp(acc+b)); 1 RES2 (vr+=..., A<-ssp(vr));
//        2 WF (vr=acc+b+u*ssp(x), A<-ssp(vr)); 3 LAST (store ssp(acc+b+vr))
// ---------------------------------------------------------------------------
__global__ void __launch_bounds__(256, 1)
tc_tail_kernel(const float* __restrict__ v_in, const float* __restrict__ x,
               const float* __restrict__ u,
               const float* __restrict__ rbint, const float* __restrict__ bf,
               const float* __restrict__ rbatm, const float* __restrict__ rbout,
               int n_int, int n_atom, int n_out,
               float* __restrict__ h_out, float* __restrict__ o_out, int N) {
    extern __shared__ uint32_t sm[];
    float* bias_s = reinterpret_cast<float*>(sm + 16384);
    float* u_s    = bias_s + 128;

    const int t = threadIdx.x, w = t >> 5, l = t & 31;
    const int g = l >> 2, m4 = l & 3;
    const int loff = l * 8;
    const int row_lo = blockIdx.x * 128 + w * 16 + g;
    const int row_hi = row_lo + 8;
    const int cb = 2 * m4;

    if (t < 32)
        reinterpret_cast<float4*>(u_s)[t] = reinterpret_cast<const float4*>(u)[t];

    float vr[64];
    uint32_t ahi[32], alo[32];
    #pragma unroll
    for (int nt = 0; nt < 16; nt++) {
        int c0 = nt * 8 + cb;
        float2 a = (row_lo < N) ? *reinterpret_cast<const float2*>(v_in + (size_t)row_lo * D + c0)
                                : make_float2(0.f, 0.f);
        float2 b = (row_hi < N) ? *reinterpret_cast<const float2*>(v_in + (size_t)row_hi * D + c0)
                                : make_float2(0.f, 0.f);
        vr[nt * 4 + 0] = a.x; vr[nt * 4 + 1] = a.y;
        vr[nt * 4 + 2] = b.x; vr[nt * 4 + 3] = b.y;
        int base = (nt >> 1) * 4 + (nt & 1) * 2;
        build_frag(sspf(a.x), sspf(a.y), ahi[base], alo[base]);
        build_frag(sspf(b.x), sspf(b.y), ahi[base + 1], alo[base + 1]);
    }

    const int total = 2 * n_int + 1 + 2 * n_atom + 2 * n_out;
    for (int s = 0; s < total; s++) {
        int mat; const float* bias; int mode; bool storeh = false;
        if (s < 2 * n_int) {
            mat = 3 + (s >> 1); bias = rbint + (size_t)(s >> 1) * D;
            mode = (s & 1) ? 1 : 0;
        } else if (s == 2 * n_int) {
            mat = 2; bias = bf; mode = 2;
            storeh = (n_atom == 0);
        } else {
            int s2 = s - 2 * n_int - 1;
            if (s2 < 2 * n_atom) {
                mat = 3 + n_int + (s2 >> 1); bias = rbatm + (size_t)(s2 >> 1) * D;
                mode = (s2 & 1) ? 1 : 0;
                storeh = (s2 == 2 * n_atom - 1);
            } else {
                int s3 = s2 - 2 * n_atom;
                mat = 3 + n_int + n_atom + (s3 >> 1); bias = rbout + (size_t)(s3 >> 1) * D;
                mode = (s3 & 1) ? ((s3 == 2 * n_out - 1) ? 3 : 1) : 0;
            }
        }

        stage_load_w(sm, bias_s, d_wimg + (size_t)mat * 16384, bias, t);
        float acc[64];
        #pragma unroll
        for (int i = 0; i < 64; i++) acc[i] = 0.0f;
        stage_mma(sm, loff, ahi, alo, acc);

        #pragma unroll
        for (int nt = 0; nt < 16; nt++) {
            int c0 = nt * 8 + cb;
            float bv0 = bias_s[c0], bv1 = bias_s[c0 + 1];
            float v0 = acc[nt * 4 + 0] + bv0;
            float v1 = acc[nt * 4 + 1] + bv1;
            float v2 = acc[nt * 4 + 2] + bv0;
            float v3 = acc[nt * 4 + 3] + bv1;
            if (mode == 1 || mode == 3) {
                v0 += vr[nt * 4 + 0]; v1 += vr[nt * 4 + 1];
                v2 += vr[nt * 4 + 2]; v3 += vr[nt * 4 + 3];
            }
            if (mode == 2) {
                float2 xl = (row_lo < N) ? *reinterpret_cast<const float2*>(x + (size_t)row_lo * D + c0)
                                         : make_float2(0.f, 0.f);
                float2 xh = (row_hi < N) ? *reinterpret_cast<const float2*>(x + (size_t)row_hi * D + c0)
                                         : make_float2(0.f, 0.f);
                float u0 = u_s[c0], u1 = u_s[c0 + 1];
                v0 += u0 * sspf(xl.x); v1 += u1 * sspf(xl.y);
                v2 += u0 * sspf(xh.x); v3 += u1 * sspf(xh.y);
            }
            if (mode == 1 || mode == 2) {
                vr[nt * 4 + 0] = v0; vr[nt * 4 + 1] = v1;
                vr[nt * 4 + 2] = v2; vr[nt * 4 + 3] = v3;
            }
            float s0 = sspf(v0), s1 = sspf(v1), s2 = sspf(v2), s3 = sspf(v3);
            if (mode == 3) {
                if (row_lo < N)
                    *reinterpret_cast<float2*>(o_out + (size_t)row_lo * D + c0) = make_float2(s0, s1);
                if (row_hi < N)
                    *reinterpret_cast<float2*>(o_out + (size_t)row_hi * D + c0) = make_float2(s2, s3);
            } else {
                int base = (nt >> 1) * 4 + (nt & 1) * 2;
                build_frag(s0, s1, ahi[base], alo[base]);
                build_frag(s2, s3, ahi[base + 1], alo[base + 1]);
            }
        }

        if (storeh) {
            #pragma unroll
            for (int nt = 0; nt < 16; nt++) {
                int c0 = nt * 8 + cb;
                if (row_lo < N)
                    *reinterpret_cast<float2*>(h_out + (size_t)row_lo * D + c0) =
                        make_float2(vr[nt * 4 + 0], vr[nt * 4 + 1]);
                if (row_hi < N)
                    *reinterpret_cast<float2*>(h_out + (size_t)row_hi * D + c0) =
                        make_float2(vr[nt * 4 + 2], vr[nt * 4 + 3]);
            }
        }
    }
}

// ---------------------------------------------------------------------------
// Edge kernel: gate = g_ij[e,:] @ Wg; v[idx_i[e],:] += gate * mj[idx_j[e],:]
// ---------------------------------------------------------------------------
__global__ __launch_bounds__(256)
void edge_kernel(const float* __restrict__ g,
                 const float* __restrict__ Wg,
                 const int* __restrict__ idx_i,
                 const int* __restrict__ idx_j,
                 const float* __restrict__ mj,
                 float* __restrict__ v,
                 int E, int R) {
    __shared__ float4 Wgs[32 * 32];
    for (int i = threadIdx.x; i < R * 32; i += blockDim.x)
        Wgs[i] = reinterpret_cast<const float4*>(Wg)[i];
    __syncthreads();

    const int lane   = threadIdx.x & 31;
    const int warp   = (blockIdx.x * blockDim.x + threadIdx.x) >> 5;
    const int nwarps = (gridDim.x * blockDim.x) >> 5;

    for (int e = warp; e < E; e += nwarps) {
        float gval = (lane < R) ? __ldg(g + (size_t)e * R + lane) : 0.0f;
        const int j = __ldg(idx_j + e);
        const int i = __ldg(idx_i + e);

        float4 acc = make_float4(0.f, 0.f, 0.f, 0.f);
        #pragma unroll 8
        for (int r = 0; r < R; r++) {
            float gr = __shfl_sync(0xffffffffu, gval, r);
            float4 wv = Wgs[r * 32 + lane];
            acc.x = fmaf(gr, wv.x, acc.x);
            acc.y = fmaf(gr, wv.y, acc.y);
            acc.z = fmaf(gr, wv.z, acc.z);
            acc.w = fmaf(gr, wv.w, acc.w);
        }

        float4 m = reinterpret_cast<const float4*>(mj)[(size_t)j * 32 + lane];
        float* vp = v + (size_t)i * D + lane * 4;
        float vx = acc.x * m.x, vy = acc.y * m.y, vz = acc.z * m.z, vw = acc.w * m.w;
        asm volatile("red.global.add.v4.f32 [%0], {%1, %2, %3, %4};"
                     :: "l"(vp), "f"(vx), "f"(vy), "f"(vz), "f"(vw) : "memory");
    }
}

// ---------------------------------------------------------------------------
// Host-side dispatch
// ---------------------------------------------------------------------------
extern "C" void kernel_launch(void* const* d_in, const int* in_sizes, int n_in,
                              void* d_out, int out_size) {
    const float* x     = (const float*)d_in[0];
    const float* g_ij  = (const float*)d_in[1];
    const float* Wf    = (const float*)d_in[2];
    const float* bf    = (const float*)d_in[3];
    const float* Wg    = (const float*)d_in[4];
    const float* Wj    = (const float*)d_in[5];
    const float* bj    = (const float*)d_in[6];
    const float* Wi    = (const float*)d_in[7];
    const float* bi    = (const float*)d_in[8];
    const float* u     = (const float*)d_in[9];
    const float* rWint = (const float*)d_in[10];
    const float* rbint = (const float*)d_in[11];
    const float* rWatm = (const float*)d_in[12];
    const float* rbatm = (const float*)d_in[13];
    const float* rWout = (const float*)d_in[14];
    const float* rbout = (const float*)d_in[15];
    const int*   idx_i = (const int*)d_in[16];
    const int*   idx_j = (const int*)d_in[17];

    const int N      = in_sizes[0] / D;
    const int E      = in_sizes[16];
    const int R      = in_sizes[4] / D;
    const int n_int  = in_sizes[11] / D;
    const int n_atom = in_sizes[13] / D;
    const int n_out  = in_sizes[15] / D;

    if (N > MAXN) return;
    const int n_mats = 3 + n_int + n_atom + n_out;
    if (n_mats > MAXMATS) return;

    float *mj, *v;
    cudaGetSymbolAddress((void**)&mj, d_mj);
    cudaGetSymbolAddress((void**)&v,  d_v);

    float* o_out = (float*)d_out;                 // o -> first N*D
    float* h_out = (float*)d_out + (size_t)N * D; // h -> second N*D

    cudaFuncSetAttribute(tc_head_kernel, cudaFuncAttributeMaxDynamicSharedMemorySize, SMEM_BYTES);
    cudaFuncSetAttribute(tc_tail_kernel, cudaFuncAttributeMaxDynamicSharedMemorySize, SMEM_BYTES);

    const int tiles = (N + 127) / 128;

    // 0) split + permute all weight matrices into bf16 hi/lo fragment images
    wsplit_kernel<<<n_mats, 256>>>(Wj, Wi, Wf, rWint, rWatm, rWout, n_int, n_atom, n_out);

    // 1) mj = ssp(ssp(x)@Wj+bj); v = ssp(ssp(x)@Wi+bi)   [HMMA]
    tc_head_kernel<<<tiles, 256, SMEM_BYTES>>>(x, bj, bi, mj, v, N);

    // 2) v += segment_sum( (g_ij @ Wg) * mj[idx_j], idx_i )
    edge_kernel<<<2048, 256>>>(g_ij, Wg, idx_i, idx_j, mj, v, E, R);

    // 3) fused register-chained tail: residual stacks + Wf + stores  [HMMA]
    tc_tail_kernel<<<tiles, 256, SMEM_BYTES>>>(
        v, x, u, rbint, bf, rbatm, rbout, n_int, n_atom, n_out, h_out, o_out, N);
}

// round 5
// speedup vs baseline: 3.2312x; 1.4399x over previous
#include <cuda_runtime.h>
#include <cuda_bf16.h>
#include <math.h>
#include <stdint.h>

#define D 128
static constexpr int MAXN = 51200;
static constexpr int MAXMATS = 16;   // slots; last used slot holds Wg frags

// ---------------------------------------------------------------------------
// Scratch (no allocs allowed -> device globals)
// ---------------------------------------------------------------------------
__device__ float d_mj[MAXN * D];
__device__ float d_v [MAXN * D];
// Pre-split, pre-permuted weight images. Per 128x128 matrix: 16384 uint32:
//   [0,8192) hi bf16x2 B-frags, [8192,16384) lo.
// Frag order: word = ((nt*8 + kt)*32 + lane)*2 + ri
//   value = pack_bf16x2(W[k0][n], W[k0+1][n]); n = nt*8+lane/4; k0 = kt*16+2*(lane%4)+ri*8
// Wg (32x128) at slot n_mats: [0,2048) hi, [2048,4096) lo with
//   word = ((nt*2 + kt)*32 + lane)*2 + ri  (kt in 0..1)
__device__ __align__(16) uint32_t d_wimg[MAXMATS * 16384];

__device__ __forceinline__ float sspf(float x) {
    return fmaxf(x, 0.0f) + __logf(1.0f + __expf(-fabsf(x))) - 0.69314718055994530942f;
}

// ---------------------------------------------------------------------------
// HMMA m16n8k16 bf16 (base PTX) + frag building
// ---------------------------------------------------------------------------
__device__ __forceinline__ void mma_bf16(float* d, const uint32_t* a,
                                         uint32_t b0, uint32_t b1) {
    asm volatile(
        "mma.sync.aligned.m16n8k16.row.col.f32.bf16.bf16.f32 "
        "{%0,%1,%2,%3}, {%4,%5,%6,%7}, {%8,%9}, {%0,%1,%2,%3};"
        : "+f"(d[0]), "+f"(d[1]), "+f"(d[2]), "+f"(d[3])
        : "r"(a[0]), "r"(a[1]), "r"(a[2]), "r"(a[3]), "r"(b0), "r"(b1));
}

__device__ __forceinline__ void build_frag(float s0, float s1,
                                           uint32_t& hi, uint32_t& lo) {
    __nv_bfloat162 h2 = __floats2bfloat162_rn(s0, s1);
    float l0 = s0 - __bfloat162float(h2.x);
    float l1 = s1 - __bfloat162float(h2.y);
    __nv_bfloat162 l2 = __floats2bfloat162_rn(l0, l1);
    hi = *reinterpret_cast<uint32_t*>(&h2);
    lo = *reinterpret_cast<uint32_t*>(&l2);
}

// ---------------------------------------------------------------------------
// cp.async helpers (base PTX, sm_80+)
// ---------------------------------------------------------------------------
__device__ __forceinline__ uint32_t smem_u32(const void* p) {
    uint32_t a;
    asm("{ .reg .u64 t; cvta.to.shared.u64 t, %1; cvt.u32.u64 %0, t; }"
        : "=r"(a) : "l"(p));
    return a;
}
#define CP_ASYNC16(dst, src) \
    asm volatile("cp.async.cg.shared.global [%0], [%1], 16;" :: "r"(dst), "l"(src))
#define CP_COMMIT() asm volatile("cp.async.commit_group;" ::: "memory")
#define CP_WAIT1()  asm volatile("cp.async.wait_group 1;"  ::: "memory")

// ---------------------------------------------------------------------------
// Weight precompute
// ---------------------------------------------------------------------------
__global__ void wsplit_kernel(const float* __restrict__ Wj,
                              const float* __restrict__ Wi,
                              const float* __restrict__ Wf,
                              const float* __restrict__ rWint,
                              const float* __restrict__ rWatm,
                              const float* __restrict__ rWout,
                              const float* __restrict__ Wg,
                              int n_int, int n_atom, int n_out) {
    int m = blockIdx.x;
    int n_mats = 3 + n_int + n_atom + n_out;

    if (m == n_mats) {  // Wg [32 x 128]
        uint32_t* hi = d_wimg + (size_t)m * 16384;
        uint32_t* lo = hi + 2048;
        for (int idx = threadIdx.x; idx < 2048; idx += blockDim.x) {
            int ri = idx & 1;
            int l  = (idx >> 1) & 31;
            int f  = idx >> 6;            // nt*2 + kt
            int kt = f & 1, nt = f >> 1;
            int n  = nt * 8 + (l >> 2);
            int k0 = kt * 16 + 2 * (l & 3) + ri * 8;
            uint32_t h, lw;
            build_frag(Wg[k0 * D + n], Wg[(k0 + 1) * D + n], h, lw);
            hi[idx] = h;
            lo[idx] = lw;
        }
        return;
    }

    const float* src;
    if (m == 0)                      src = Wj;
    else if (m == 1)                 src = Wi;
    else if (m == 2)                 src = Wf;
    else if (m < 3 + n_int)          src = rWint + (size_t)(m - 3) * D * D;
    else if (m < 3 + n_int + n_atom) src = rWatm + (size_t)(m - 3 - n_int) * D * D;
    else                             src = rWout + (size_t)(m - 3 - n_int - n_atom) * D * D;

    uint32_t* hi = d_wimg + (size_t)m * 16384;
    uint32_t* lo = hi + 8192;

    for (int idx = threadIdx.x; idx < 8192; idx += blockDim.x) {
        int ri = idx & 1;
        int l  = (idx >> 1) & 31;
        int f  = idx >> 6;            // nt*8 + kt
        int kt = f & 7, nt = f >> 3;
        int n  = nt * 8 + (l >> 2);
        int k0 = kt * 16 + 2 * (l & 3) + ri * 8;
        uint32_t h, lw;
        build_frag(src[k0 * D + n], src[(k0 + 1) * D + n], h, lw);
        hi[idx] = h;
        lo[idx] = lw;
    }
}

// ---------------------------------------------------------------------------
// Shared MMA stage helpers (8 warps, warp owns 16 rows)
// ---------------------------------------------------------------------------
__device__ __forceinline__ void stage_mma(const uint32_t* wsm, int loff,
                                          const uint32_t* ahi, const uint32_t* alo,
                                          float* acc) {
    const char* base = reinterpret_cast<const char*>(wsm);
    #pragma unroll
    for (int kt = 0; kt < 8; kt++) {
        #pragma unroll
        for (int nt = 0; nt < 16; nt++) {
            uint2 bh = *reinterpret_cast<const uint2*>(base + (nt * 8 + kt) * 256 + loff);
            mma_bf16(acc + nt * 4, ahi + kt * 4, bh.x, bh.y);
            mma_bf16(acc + nt * 4, alo + kt * 4, bh.x, bh.y);
            uint2 bl = *reinterpret_cast<const uint2*>(base + 32768 + (nt * 8 + kt) * 256 + loff);
            mma_bf16(acc + nt * 4, ahi + kt * 4, bl.x, bl.y);
        }
    }
}

// ---------------------------------------------------------------------------
// Head kernel: A = ssp(x); mj = ssp(A@Wj+bj); v = ssp(A@Wi+bi)
// (synchronous weight load; only 2 stages)
// ---------------------------------------------------------------------------
static constexpr int HEAD_SMEM = (16384 + 128) * 4;

__global__ void __launch_bounds__(256, 1)
tc_head_kernel(const float* __restrict__ x,
               const float* __restrict__ bj, const float* __restrict__ bi,
               float* __restrict__ mj, float* __restrict__ v, int N) {
    extern __shared__ uint32_t sm[];
    float* bias_s = reinterpret_cast<float*>(sm + 16384);

    const int t = threadIdx.x, w = t >> 5, l = t & 31;
    const int g = l >> 2, m4 = l & 3;
    const int loff = l * 8;
    const int row_lo = blockIdx.x * 128 + w * 16 + g;
    const int row_hi = row_lo + 8;
    const int cb = 2 * m4;

    uint32_t ahi[32], alo[32];
    #pragma unroll
    for (int nt = 0; nt < 16; nt++) {
        int c0 = nt * 8 + cb;
        float2 a = (row_lo < N) ? *reinterpret_cast<const float2*>(x + (size_t)row_lo * D + c0)
                                : make_float2(0.f, 0.f);
        float2 b = (row_hi < N) ? *reinterpret_cast<const float2*>(x + (size_t)row_hi * D + c0)
                                : make_float2(0.f, 0.f);
        int base = (nt >> 1) * 4 + (nt & 1) * 2;
        build_frag(sspf(a.x), sspf(a.y), ahi[base], alo[base]);
        build_frag(sspf(b.x), sspf(b.y), ahi[base + 1], alo[base + 1]);
    }

    for (int s = 0; s < 2; s++) {
        __syncthreads();
        const uint4* src = reinterpret_cast<const uint4*>(d_wimg + (size_t)s * 16384);
        uint4* dst = reinterpret_cast<uint4*>(sm);
        #pragma unroll
        for (int i = 0; i < 16; i++)
            dst[t + 256 * i] = src[t + 256 * i];
        if (t < 32)
            reinterpret_cast<float4*>(bias_s)[t] =
                reinterpret_cast<const float4*>(s ? bi : bj)[t];
        __syncthreads();

        float acc[64];
        #pragma unroll
        for (int i = 0; i < 64; i++) acc[i] = 0.0f;
        stage_mma(sm, loff, ahi, alo, acc);

        float* outp = s ? v : mj;
        #pragma unroll
        for (int nt = 0; nt < 16; nt++) {
            int c0 = nt * 8 + cb;
            float bv0 = bias_s[c0], bv1 = bias_s[c0 + 1];
            float s0 = sspf(acc[nt * 4 + 0] + bv0);
            float s1 = sspf(acc[nt * 4 + 1] + bv1);
            float s2 = sspf(acc[nt * 4 + 2] + bv0);
            float s3 = sspf(acc[nt * 4 + 3] + bv1);
            if (row_lo < N)
                *reinterpret_cast<float2*>(outp + (size_t)row_lo * D + c0) = make_float2(s0, s1);
            if (row_hi < N)
                *reinterpret_cast<float2*>(outp + (size_t)row_hi * D + c0) = make_float2(s2, s3);
        }
    }
}

// ---------------------------------------------------------------------------
// Tail kernel: register-chained stage loop with cp.async double-buffered W.
// Buffer layout (words): [0,16384) W frags, [16384,16512) bias. Two buffers.
// ---------------------------------------------------------------------------
static constexpr int BUFW = 16512;                    // words per buffer
static constexpr int TAIL_SMEM = (2 * BUFW + 128) * 4; // + u (128 words)

__device__ __forceinline__ void issue_stage_copy(uint32_t buf_addr,
                                                 const uint32_t* img,
                                                 const float* bias, int t) {
    #pragma unroll
    for (int i = 0; i < 16; i++)
        CP_ASYNC16(buf_addr + (t + 256 * i) * 16, img + (t + 256 * i) * 4);
    if (t < 32)
        CP_ASYNC16(buf_addr + 16384 * 4 + t * 16, bias + t * 4);
}

__global__ void __launch_bounds__(256, 1)
tc_tail_kernel(const float* __restrict__ v_in, const float* __restrict__ x,
               const float* __restrict__ u,
               const float* __restrict__ rbint, const float* __restrict__ bf,
               const float* __restrict__ rbatm, const float* __restrict__ rbout,
               int n_int, int n_atom, int n_out,
               float* __restrict__ h_out, float* __restrict__ o_out, int N) {
    extern __shared__ uint32_t sm[];
    float* u_s = reinterpret_cast<float*>(sm + 2 * BUFW);
    const uint32_t sm_addr = smem_u32(sm);

    const int t = threadIdx.x, w = t >> 5, l = t & 31;
    const int g = l >> 2, m4 = l & 3;
    const int loff = l * 8;
    const int row_lo = blockIdx.x * 128 + w * 16 + g;
    const int row_hi = row_lo + 8;
    const int cb = 2 * m4;

    if (t < 32)
        reinterpret_cast<float4*>(u_s)[t] = reinterpret_cast<const float4*>(u)[t];

    const int total = 2 * n_int + 1 + 2 * n_atom + 2 * n_out;

    // stage descriptor
    auto stage_desc = [&](int s, int& mat, const float*& bias, int& mode, bool& storeh) {
        storeh = false;
        if (s < 2 * n_int) {
            mat = 3 + (s >> 1); bias = rbint + (size_t)(s >> 1) * D;
            mode = (s & 1) ? 1 : 0;
        } else if (s == 2 * n_int) {
            mat = 2; bias = bf; mode = 2; storeh = (n_atom == 0);
        } else {
            int s2 = s - 2 * n_int - 1;
            if (s2 < 2 * n_atom) {
                mat = 3 + n_int + (s2 >> 1); bias = rbatm + (size_t)(s2 >> 1) * D;
                mode = (s2 & 1) ? 1 : 0;
                storeh = (s2 == 2 * n_atom - 1);
            } else {
                int s3 = s2 - 2 * n_atom;
                mat = 3 + n_int + n_atom + (s3 >> 1); bias = rbout + (size_t)(s3 >> 1) * D;
                mode = (s3 & 1) ? ((s3 == 2 * n_out - 1) ? 3 : 1) : 0;
            }
        }
    };

    // prologue: prefetch stage 0
    {
        int mat; const float* bias; int mode; bool sh;
        stage_desc(0, mat, bias, mode, sh);
        issue_stage_copy(sm_addr, d_wimg + (size_t)mat * 16384, bias, t);
        CP_COMMIT();
    }

    // init fragments + residual carry
    float vr[64];
    uint32_t ahi[32], alo[32];
    #pragma unroll
    for (int nt = 0; nt < 16; nt++) {
        int c0 = nt * 8 + cb;
        float2 a = (row_lo < N) ? *reinterpret_cast<const float2*>(v_in + (size_t)row_lo * D + c0)
                                : make_float2(0.f, 0.f);
        float2 b = (row_hi < N) ? *reinterpret_cast<const float2*>(v_in + (size_t)row_hi * D + c0)
                                : make_float2(0.f, 0.f);
        vr[nt * 4 + 0] = a.x; vr[nt * 4 + 1] = a.y;
        vr[nt * 4 + 2] = b.x; vr[nt * 4 + 3] = b.y;
        int base = (nt >> 1) * 4 + (nt & 1) * 2;
        build_frag(sspf(a.x), sspf(a.y), ahi[base], alo[base]);
        build_frag(sspf(b.x), sspf(b.y), ahi[base + 1], alo[base + 1]);
    }

    for (int s = 0; s < total; s++) {
        int mat; const float* bias; int mode; bool storeh;
        stage_desc(s, mat, bias, mode, storeh);

        // prefetch next stage into the other buffer (protected by prev iter's sync)
        if (s + 1 < total) {
            int nmat; const float* nbias; int nmode; bool nsh;
            stage_desc(s + 1, nmat, nbias, nmode, nsh);
            issue_stage_copy(sm_addr + ((s + 1) & 1) * BUFW * 4,
                             d_wimg + (size_t)nmat * 16384, nbias, t);
        }
        CP_COMMIT();
        CP_WAIT1();            // current stage's buffer landed
        __syncthreads();

        const uint32_t* wbuf = sm + (s & 1) * BUFW;
        const float* bias_s = reinterpret_cast<const float*>(wbuf + 16384);

        float acc[64];
        #pragma unroll
        for (int i = 0; i < 64; i++) acc[i] = 0.0f;
        stage_mma(wbuf, loff, ahi, alo, acc);

        #pragma unroll
        for (int nt = 0; nt < 16; nt++) {
            int c0 = nt * 8 + cb;
            float bv0 = bias_s[c0], bv1 = bias_s[c0 + 1];
            float v0 = acc[nt * 4 + 0] + bv0;
            float v1 = acc[nt * 4 + 1] + bv1;
            float v2 = acc[nt * 4 + 2] + bv0;
            float v3 = acc[nt * 4 + 3] + bv1;
            if (mode == 1 || mode == 3) {
                v0 += vr[nt * 4 + 0]; v1 += vr[nt * 4 + 1];
                v2 += vr[nt * 4 + 2]; v3 += vr[nt * 4 + 3];
            }
            if (mode == 2) {
                float2 xl = (row_lo < N) ? *reinterpret_cast<const float2*>(x + (size_t)row_lo * D + c0)
                                         : make_float2(0.f, 0.f);
                float2 xh = (row_hi < N) ? *reinterpret_cast<const float2*>(x + (size_t)row_hi * D + c0)
                                         : make_float2(0.f, 0.f);
                float u0 = u_s[c0], u1 = u_s[c0 + 1];
                v0 += u0 * sspf(xl.x); v1 += u1 * sspf(xl.y);
                v2 += u0 * sspf(xh.x); v3 += u1 * sspf(xh.y);
            }
            if (mode == 1 || mode == 2) {
                vr[nt * 4 + 0] = v0; vr[nt * 4 + 1] = v1;
                vr[nt * 4 + 2] = v2; vr[nt * 4 + 3] = v3;
            }
            float s0 = sspf(v0), s1 = sspf(v1), s2 = sspf(v2), s3 = sspf(v3);
            if (mode == 3) {
                if (row_lo < N)
                    *reinterpret_cast<float2*>(o_out + (size_t)row_lo * D + c0) = make_float2(s0, s1);
                if (row_hi < N)
                    *reinterpret_cast<float2*>(o_out + (size_t)row_hi * D + c0) = make_float2(s2, s3);
            } else {
                int base = (nt >> 1) * 4 + (nt & 1) * 2;
                build_frag(s0, s1, ahi[base], alo[base]);
                build_frag(s2, s3, ahi[base + 1], alo[base + 1]);
            }
        }

        if (storeh) {
            #pragma unroll
            for (int nt = 0; nt < 16; nt++) {
                int c0 = nt * 8 + cb;
                if (row_lo < N)
                    *reinterpret_cast<float2*>(h_out + (size_t)row_lo * D + c0) =
                        make_float2(vr[nt * 4 + 0], vr[nt * 4 + 1]);
                if (row_hi < N)
                    *reinterpret_cast<float2*>(h_out + (size_t)row_hi * D + c0) =
                        make_float2(vr[nt * 4 + 2], vr[nt * 4 + 3]);
            }
        }
        __syncthreads();   // all warps done with wbuf before it is overwritten
    }
}

// ---------------------------------------------------------------------------
// Edge kernel (HMMA gate): one warp processes 16 edges.
//   gate[16,128] = g[16,32] @ Wg  (bf16 hi/lo split, fp32 acc, tensor pipe)
//   v[idx_i[e], :] += gate[e,:] * mj[idx_j[e], :]   (red.v2)
// ---------------------------------------------------------------------------
__global__ __launch_bounds__(256)
void edge_mma_kernel(const float* __restrict__ g,
                     const int* __restrict__ idx_i,
                     const int* __restrict__ idx_j,
                     const float* __restrict__ mj,
                     float* __restrict__ v,
                     int E, int wg_slot) {
    __shared__ uint32_t wgs[4096];   // Wg frags: hi[2048] + lo[2048]
    {
        const uint4* src = reinterpret_cast<const uint4*>(d_wimg + (size_t)wg_slot * 16384);
        uint4* dst = reinterpret_cast<uint4*>(wgs);
        #pragma unroll
        for (int i = threadIdx.x; i < 1024; i += 256)
            dst[i] = src[i];
    }
    __syncthreads();

    const int t = threadIdx.x, l = t & 31;
    const int gq = l >> 2, m4 = l & 3;
    const int batch = blockIdx.x * 8 + (t >> 5);
    const int e0 = batch * 16;
    if (e0 >= E) return;

    const int r0 = e0 + gq, r1 = r0 + 8;
    const bool v0ok = (r0 < E), v1ok = (r1 < E);
    const int j0 = v0ok ? __ldg(idx_j + r0) : 0;
    const int i0 = v0ok ? __ldg(idx_i + r0) : 0;
    const int j1 = v1ok ? __ldg(idx_j + r1) : 0;
    const int i1 = v1ok ? __ldg(idx_i + r1) : 0;

    // A fragments from g rows (R=32 -> 2 ktiles)
    uint32_t ahi[8], alo[8];
    #pragma unroll
    for (int kt = 0; kt < 2; kt++) {
        int kb = kt * 16 + 2 * m4;
        float2 p00 = v0ok ? *reinterpret_cast<const float2*>(g + (size_t)r0 * 32 + kb)
                          : make_float2(0.f, 0.f);
        float2 p01 = v0ok ? *reinterpret_cast<const float2*>(g + (size_t)r0 * 32 + kb + 8)
                          : make_float2(0.f, 0.f);
        float2 p10 = v1ok ? *reinterpret_cast<const float2*>(g + (size_t)r1 * 32 + kb)
                          : make_float2(0.f, 0.f);
        float2 p11 = v1ok ? *reinterpret_cast<const float2*>(g + (size_t)r1 * 32 + kb + 8)
                          : make_float2(0.f, 0.f);
        build_frag(p00.x, p00.y, ahi[kt * 4 + 0], alo[kt * 4 + 0]);
        build_frag(p10.x, p10.y, ahi[kt * 4 + 1], alo[kt * 4 + 1]);
        build_frag(p01.x, p01.y, ahi[kt * 4 + 2], alo[kt * 4 + 2]);
        build_frag(p11.x, p11.y, ahi[kt * 4 + 3], alo[kt * 4 + 3]);
    }

    float acc[64];
    #pragma unroll
    for (int i = 0; i < 64; i++) acc[i] = 0.0f;

    const char* base = reinterpret_cast<const char*>(wgs);
    const int loff = l * 8;
    #pragma unroll
    for (int nt = 0; nt < 16; nt++) {
        #pragma unroll
        for (int kt = 0; kt < 2; kt++) {
            uint2 bh = *reinterpret_cast<const uint2*>(base + (nt * 2 + kt) * 256 + loff);
            mma_bf16(acc + nt * 4, ahi + kt * 4, bh.x, bh.y);
            mma_bf16(acc + nt * 4, alo + kt * 4, bh.x, bh.y);
            uint2 bl = *reinterpret_cast<const uint2*>(base + 8192 + (nt * 2 + kt) * 256 + loff);
            mma_bf16(acc + nt * 4, ahi + kt * 4, bl.x, bl.y);
        }
    }

    // scatter: v[i,:] += gate * mj[j,:]
    #pragma unroll
    for (int nt = 0; nt < 16; nt++) {
        int c0 = nt * 8 + 2 * m4;
        if (v0ok) {
            float2 m0 = *reinterpret_cast<const float2*>(mj + (size_t)j0 * D + c0);
            float x0 = acc[nt * 4 + 0] * m0.x;
            float y0 = acc[nt * 4 + 1] * m0.y;
            asm volatile("red.global.add.v2.f32 [%0], {%1, %2};"
                         :: "l"(v + (size_t)i0 * D + c0), "f"(x0), "f"(y0) : "memory");
        }
        if (v1ok) {
            float2 m1 = *reinterpret_cast<const float2*>(mj + (size_t)j1 * D + c0);
            float x1 = acc[nt * 4 + 2] * m1.x;
            float y1 = acc[nt * 4 + 3] * m1.y;
            asm volatile("red.global.add.v2.f32 [%0], {%1, %2};"
                         :: "l"(v + (size_t)i1 * D + c0), "f"(x1), "f"(y1) : "memory");
        }
    }
}

// ---------------------------------------------------------------------------
// Host-side dispatch
// ---------------------------------------------------------------------------
extern "C" void kernel_launch(void* const* d_in, const int* in_sizes, int n_in,
                              void* d_out, int out_size) {
    const float* x     = (const float*)d_in[0];
    const float* g_ij  = (const float*)d_in[1];
    const float* Wf    = (const float*)d_in[2];
    const float* bf    = (const float*)d_in[3];
    const float* Wg    = (const float*)d_in[4];
    const float* Wj    = (const float*)d_in[5];
    const float* bj    = (const float*)d_in[6];
    const float* Wi    = (const float*)d_in[7];
    const float* bi    = (const float*)d_in[8];
    const float* u     = (const float*)d_in[9];
    const float* rWint = (const float*)d_in[10];
    const float* rbint = (const float*)d_in[11];
    const float* rWatm = (const float*)d_in[12];
    const float* rbatm = (const float*)d_in[13];
    const float* rWout = (const float*)d_in[14];
    const float* rbout = (const float*)d_in[15];
    const int*   idx_i = (const int*)d_in[16];
    const int*   idx_j = (const int*)d_in[17];

    const int N      = in_sizes[0] / D;
    const int E      = in_sizes[16];
    const int n_int  = in_sizes[11] / D;
    const int n_atom = in_sizes[13] / D;
    const int n_out  = in_sizes[15] / D;

    if (N > MAXN) return;
    const int n_mats = 3 + n_int + n_atom + n_out;
    if (n_mats + 1 > MAXMATS) return;

    float *mj, *v;
    cudaGetSymbolAddress((void**)&mj, d_mj);
    cudaGetSymbolAddress((void**)&v,  d_v);

    float* o_out = (float*)d_out;                 // o -> first N*D
    float* h_out = (float*)d_out + (size_t)N * D; // h -> second N*D

    cudaFuncSetAttribute(tc_head_kernel, cudaFuncAttributeMaxDynamicSharedMemorySize, HEAD_SMEM);
    cudaFuncSetAttribute(tc_tail_kernel, cudaFuncAttributeMaxDynamicSharedMemorySize, TAIL_SMEM);

    const int tiles = (N + 127) / 128;

    // 0) split + permute weights (incl. Wg at slot n_mats)
    wsplit_kernel<<<n_mats + 1, 256>>>(Wj, Wi, Wf, rWint, rWatm, rWout, Wg,
                                       n_int, n_atom, n_out);

    // 1) mj = ssp(ssp(x)@Wj+bj); v = ssp(ssp(x)@Wi+bi)
    tc_head_kernel<<<tiles, 256, HEAD_SMEM>>>(x, bj, bi, mj, v, N);

    // 2) v += segment_sum( (g_ij @ Wg) * mj[idx_j], idx_i )   [HMMA gate]
    {
        int batches = (E + 15) / 16;
        int blocks  = (batches + 7) / 8;
        edge_mma_kernel<<<blocks, 256>>>(g_ij, idx_i, idx_j, mj, v, E, n_mats);
    }

    // 3) fused register-chained tail with prefetched weights
    tc_tail_kernel<<<tiles, 256, TAIL_SMEM>>>(
        v, x, u, rbint, bf, rbatm, rbout, n_int, n_atom, n_out, h_out, o_out, N);
}

// round 6
// speedup vs baseline: 3.5017x; 1.0837x over previous
#include <cuda_runtime.h>
#include <cuda_bf16.h>
#include <math.h>
#include <stdint.h>

#define D 128
static constexpr int MAXN = 51200;
static constexpr int MAXMATS = 16;   // slots; last used slot holds Wg frags

// ---------------------------------------------------------------------------
// Scratch (no allocs allowed -> device globals)
// ---------------------------------------------------------------------------
__device__ float d_mj[MAXN * D];
__device__ float d_v [MAXN * D];
// Pre-split, pre-permuted weight images. Per 128x128 matrix: 16384 uint32:
//   [0,8192) hi bf16x2 B-frags, [8192,16384) lo.
// Frag order: word = ((nt*8 + kt)*32 + lane)*2 + ri
//   value = pack_bf16x2(W[k0][n], W[k0+1][n]); n = nt*8+lane/4; k0 = kt*16+2*(lane%4)+ri*8
// Wg (32x128) at slot n_mats: [0,2048) hi, [2048,4096) lo with
//   word = ((nt*2 + kt)*32 + lane)*2 + ri  (kt in 0..1)
__device__ __align__(16) uint32_t d_wimg[MAXMATS * 16384];

__device__ __forceinline__ float sspf(float x) {
    return fmaxf(x, 0.0f) + __logf(1.0f + __expf(-fabsf(x))) - 0.69314718055994530942f;
}

// ---------------------------------------------------------------------------
// HMMA m16n8k16 bf16 (base PTX) + frag building
// ---------------------------------------------------------------------------
__device__ __forceinline__ void mma_bf16(float* d, const uint32_t* a,
                                         uint32_t b0, uint32_t b1) {
    asm volatile(
        "mma.sync.aligned.m16n8k16.row.col.f32.bf16.bf16.f32 "
        "{%0,%1,%2,%3}, {%4,%5,%6,%7}, {%8,%9}, {%0,%1,%2,%3};"
        : "+f"(d[0]), "+f"(d[1]), "+f"(d[2]), "+f"(d[3])
        : "r"(a[0]), "r"(a[1]), "r"(a[2]), "r"(a[3]), "r"(b0), "r"(b1));
}

__device__ __forceinline__ void build_frag(float s0, float s1,
                                           uint32_t& hi, uint32_t& lo) {
    __nv_bfloat162 h2 = __floats2bfloat162_rn(s0, s1);
    float l0 = s0 - __bfloat162float(h2.x);
    float l1 = s1 - __bfloat162float(h2.y);
    __nv_bfloat162 l2 = __floats2bfloat162_rn(l0, l1);
    hi = *reinterpret_cast<uint32_t*>(&h2);
    lo = *reinterpret_cast<uint32_t*>(&l2);
}

// ---------------------------------------------------------------------------
// cp.async helpers (base PTX, sm_80+)
// ---------------------------------------------------------------------------
__device__ __forceinline__ uint32_t smem_u32(const void* p) {
    uint32_t a;
    asm("{ .reg .u64 t; cvta.to.shared.u64 t, %1; cvt.u32.u64 %0, t; }"
        : "=r"(a) : "l"(p));
    return a;
}
#define CP_ASYNC16(dst, src) \
    asm volatile("cp.async.cg.shared.global [%0], [%1], 16;" :: "r"(dst), "l"(src))
#define CP_COMMIT() asm volatile("cp.async.commit_group;" ::: "memory")
#define CP_WAIT1()  asm volatile("cp.async.wait_group 1;"  ::: "memory")

// ---------------------------------------------------------------------------
// Weight precompute (8 blocks per matrix for parallelism)
// ---------------------------------------------------------------------------
__global__ void wsplit_kernel(const float* __restrict__ Wj,
                              const float* __restrict__ Wi,
                              const float* __restrict__ Wf,
                              const float* __restrict__ rWint,
                              const float* __restrict__ rWatm,
                              const float* __restrict__ rWout,
                              const float* __restrict__ Wg,
                              int n_int, int n_atom, int n_out) {
    int m    = blockIdx.x >> 3;
    int part = blockIdx.x & 7;
    int n_mats = 3 + n_int + n_atom + n_out;

    if (m == n_mats) {  // Wg [32 x 128]
        uint32_t* hi = d_wimg + (size_t)m * 16384;
        uint32_t* lo = hi + 2048;
        for (int idx = part * 256 + threadIdx.x; idx < 2048; idx += 2048) {
            int ri = idx & 1;
            int l  = (idx >> 1) & 31;
            int f  = idx >> 6;            // nt*2 + kt
            int kt = f & 1, nt = f >> 1;
            int n  = nt * 8 + (l >> 2);
            int k0 = kt * 16 + 2 * (l & 3) + ri * 8;
            uint32_t h, lw;
            build_frag(Wg[k0 * D + n], Wg[(k0 + 1) * D + n], h, lw);
            hi[idx] = h;
            lo[idx] = lw;
        }
        return;
    }

    const float* src;
    if (m == 0)                      src = Wj;
    else if (m == 1)                 src = Wi;
    else if (m == 2)                 src = Wf;
    else if (m < 3 + n_int)          src = rWint + (size_t)(m - 3) * D * D;
    else if (m < 3 + n_int + n_atom) src = rWatm + (size_t)(m - 3 - n_int) * D * D;
    else                             src = rWout + (size_t)(m - 3 - n_int - n_atom) * D * D;

    uint32_t* hi = d_wimg + (size_t)m * 16384;
    uint32_t* lo = hi + 8192;

    for (int idx = part * 1024 + threadIdx.x; idx < (part + 1) * 1024; idx += 256) {
        int ri = idx & 1;
        int l  = (idx >> 1) & 31;
        int f  = idx >> 6;            // nt*8 + kt
        int kt = f & 7, nt = f >> 3;
        int n  = nt * 8 + (l >> 2);
        int k0 = kt * 16 + 2 * (l & 3) + ri * 8;
        uint32_t h, lw;
        build_frag(src[k0 * D + n], src[(k0 + 1) * D + n], h, lw);
        hi[idx] = h;
        lo[idx] = lw;
    }
}

// ---------------------------------------------------------------------------
// MMA stage: pass-separated, B chunked into registers (4 nt at a time) so
// same-accumulator HMMAs are >=4 apart (hides accumulation RAW latency).
// ---------------------------------------------------------------------------
__device__ __forceinline__ void stage_mma(const uint32_t* wsm, int loff,
                                          const uint32_t* ahi, const uint32_t* alo,
                                          float* acc) {
    const char* base = reinterpret_cast<const char*>(wsm);
    #pragma unroll
    for (int kt = 0; kt < 8; kt++) {
        #pragma unroll
        for (int c = 0; c < 4; c++) {
            uint2 bh[4], bl[4];
            #pragma unroll
            for (int i = 0; i < 4; i++)
                bh[i] = *reinterpret_cast<const uint2*>(base + ((c * 4 + i) * 8 + kt) * 256 + loff);
            #pragma unroll
            for (int i = 0; i < 4; i++)
                bl[i] = *reinterpret_cast<const uint2*>(base + 32768 + ((c * 4 + i) * 8 + kt) * 256 + loff);
            #pragma unroll
            for (int i = 0; i < 4; i++)
                mma_bf16(acc + (c * 4 + i) * 4, ahi + kt * 4, bh[i].x, bh[i].y);
            #pragma unroll
            for (int i = 0; i < 4; i++)
                mma_bf16(acc + (c * 4 + i) * 4, alo + kt * 4, bh[i].x, bh[i].y);
            #pragma unroll
            for (int i = 0; i < 4; i++)
                mma_bf16(acc + (c * 4 + i) * 4, ahi + kt * 4, bl[i].x, bl[i].y);
        }
    }
}

// ---------------------------------------------------------------------------
// Head kernel: A = ssp(x); mj = ssp(A@Wj+bj); v = ssp(A@Wi+bi)
// ---------------------------------------------------------------------------
static constexpr int HEAD_SMEM = (16384 + 128) * 4;

__global__ void __launch_bounds__(256, 1)
tc_head_kernel(const float* __restrict__ x,
               const float* __restrict__ bj, const float* __restrict__ bi,
               float* __restrict__ mj, float* __restrict__ v, int N) {
    extern __shared__ uint32_t sm[];
    float* bias_s = reinterpret_cast<float*>(sm + 16384);

    const int t = threadIdx.x, w = t >> 5, l = t & 31;
    const int g = l >> 2, m4 = l & 3;
    const int loff = l * 8;
    const int row_lo = blockIdx.x * 128 + w * 16 + g;
    const int row_hi = row_lo + 8;
    const int cb = 2 * m4;

    uint32_t ahi[32], alo[32];
    #pragma unroll
    for (int nt = 0; nt < 16; nt++) {
        int c0 = nt * 8 + cb;
        float2 a = (row_lo < N) ? *reinterpret_cast<const float2*>(x + (size_t)row_lo * D + c0)
                                : make_float2(0.f, 0.f);
        float2 b = (row_hi < N) ? *reinterpret_cast<const float2*>(x + (size_t)row_hi * D + c0)
                                : make_float2(0.f, 0.f);
        int base = (nt >> 1) * 4 + (nt & 1) * 2;
        build_frag(sspf(a.x), sspf(a.y), ahi[base], alo[base]);
        build_frag(sspf(b.x), sspf(b.y), ahi[base + 1], alo[base + 1]);
    }

    for (int s = 0; s < 2; s++) {
        __syncthreads();
        const uint4* src = reinterpret_cast<const uint4*>(d_wimg + (size_t)s * 16384);
        uint4* dst = reinterpret_cast<uint4*>(sm);
        #pragma unroll
        for (int i = 0; i < 16; i++)
            dst[t + 256 * i] = src[t + 256 * i];
        if (t < 32)
            reinterpret_cast<float4*>(bias_s)[t] =
                reinterpret_cast<const float4*>(s ? bi : bj)[t];
        __syncthreads();

        float acc[64];
        #pragma unroll
        for (int i = 0; i < 64; i++) acc[i] = 0.0f;
        stage_mma(sm, loff, ahi, alo, acc);

        float* outp = s ? v : mj;
        #pragma unroll
        for (int nt = 0; nt < 16; nt++) {
            int c0 = nt * 8 + cb;
            float bv0 = bias_s[c0], bv1 = bias_s[c0 + 1];
            float s0 = sspf(acc[nt * 4 + 0] + bv0);
            float s1 = sspf(acc[nt * 4 + 1] + bv1);
            float s2 = sspf(acc[nt * 4 + 2] + bv0);
            float s3 = sspf(acc[nt * 4 + 3] + bv1);
            if (row_lo < N)
                *reinterpret_cast<float2*>(outp + (size_t)row_lo * D + c0) = make_float2(s0, s1);
            if (row_hi < N)
                *reinterpret_cast<float2*>(outp + (size_t)row_hi * D + c0) = make_float2(s2, s3);
        }
    }
}

// ---------------------------------------------------------------------------
// Tail kernel: register-chained stage loop with cp.async double-buffered W.
// ---------------------------------------------------------------------------
static constexpr int BUFW = 16512;                    // words per buffer
static constexpr int TAIL_SMEM = (2 * BUFW + 128) * 4;

__device__ __forceinline__ void issue_stage_copy(uint32_t buf_addr,
                                                 const uint32_t* img,
                                                 const float* bias, int t) {
    #pragma unroll
    for (int i = 0; i < 16; i++)
        CP_ASYNC16(buf_addr + (t + 256 * i) * 16, img + (t + 256 * i) * 4);
    if (t < 32)
        CP_ASYNC16(buf_addr + 16384 * 4 + t * 16, bias + t * 4);
}

__global__ void __launch_bounds__(256, 1)
tc_tail_kernel(const float* __restrict__ v_in, const float* __restrict__ x,
               const float* __restrict__ u,
               const float* __restrict__ rbint, const float* __restrict__ bf,
               const float* __restrict__ rbatm, const float* __restrict__ rbout,
               int n_int, int n_atom, int n_out,
               float* __restrict__ h_out, float* __restrict__ o_out, int N) {
    extern __shared__ uint32_t sm[];
    float* u_s = reinterpret_cast<float*>(sm + 2 * BUFW);
    const uint32_t sm_addr = smem_u32(sm);

    const int t = threadIdx.x, w = t >> 5, l = t & 31;
    const int g = l >> 2, m4 = l & 3;
    const int loff = l * 8;
    const int row_lo = blockIdx.x * 128 + w * 16 + g;
    const int row_hi = row_lo + 8;
    const int cb = 2 * m4;

    if (t < 32)
        reinterpret_cast<float4*>(u_s)[t] = reinterpret_cast<const float4*>(u)[t];

    const int total = 2 * n_int + 1 + 2 * n_atom + 2 * n_out;

    auto stage_desc = [&](int s, int& mat, const float*& bias, int& mode, bool& storeh) {
        storeh = false;
        if (s < 2 * n_int) {
            mat = 3 + (s >> 1); bias = rbint + (size_t)(s >> 1) * D;
            mode = (s & 1) ? 1 : 0;
        } else if (s == 2 * n_int) {
            mat = 2; bias = bf; mode = 2; storeh = (n_atom == 0);
        } else {
            int s2 = s - 2 * n_int - 1;
            if (s2 < 2 * n_atom) {
                mat = 3 + n_int + (s2 >> 1); bias = rbatm + (size_t)(s2 >> 1) * D;
                mode = (s2 & 1) ? 1 : 0;
                storeh = (s2 == 2 * n_atom - 1);
            } else {
                int s3 = s2 - 2 * n_atom;
                mat = 3 + n_int + n_atom + (s3 >> 1); bias = rbout + (size_t)(s3 >> 1) * D;
                mode = (s3 & 1) ? ((s3 == 2 * n_out - 1) ? 3 : 1) : 0;
            }
        }
    };

    // prologue: prefetch stage 0
    {
        int mat; const float* bias; int mode; bool sh;
        stage_desc(0, mat, bias, mode, sh);
        issue_stage_copy(sm_addr, d_wimg + (size_t)mat * 16384, bias, t);
        CP_COMMIT();
    }

    // init fragments + residual carry
    float vr[64];
    uint32_t ahi[32], alo[32];
    #pragma unroll
    for (int nt = 0; nt < 16; nt++) {
        int c0 = nt * 8 + cb;
        float2 a = (row_lo < N) ? *reinterpret_cast<const float2*>(v_in + (size_t)row_lo * D + c0)
                                : make_float2(0.f, 0.f);
        float2 b = (row_hi < N) ? *reinterpret_cast<const float2*>(v_in + (size_t)row_hi * D + c0)
                                : make_float2(0.f, 0.f);
        vr[nt * 4 + 0] = a.x; vr[nt * 4 + 1] = a.y;
        vr[nt * 4 + 2] = b.x; vr[nt * 4 + 3] = b.y;
        int base = (nt >> 1) * 4 + (nt & 1) * 2;
        build_frag(sspf(a.x), sspf(a.y), ahi[base], alo[base]);
        build_frag(sspf(b.x), sspf(b.y), ahi[base + 1], alo[base + 1]);
    }

    for (int s = 0; s < total; s++) {
        int mat; const float* bias; int mode; bool storeh;
        stage_desc(s, mat, bias, mode, storeh);

        if (s + 1 < total) {
            int nmat; const float* nbias; int nmode; bool nsh;
            stage_desc(s + 1, nmat, nbias, nmode, nsh);
            issue_stage_copy(sm_addr + ((s + 1) & 1) * BUFW * 4,
                             d_wimg + (size_t)nmat * 16384, nbias, t);
        }
        CP_COMMIT();
        CP_WAIT1();
        __syncthreads();

        const uint32_t* wbuf = sm + (s & 1) * BUFW;
        const float* bias_s = reinterpret_cast<const float*>(wbuf + 16384);

        float acc[64];
        #pragma unroll
        for (int i = 0; i < 64; i++) acc[i] = 0.0f;
        stage_mma(wbuf, loff, ahi, alo, acc);

        #pragma unroll
        for (int nt = 0; nt < 16; nt++) {
            int c0 = nt * 8 + cb;
            float bv0 = bias_s[c0], bv1 = bias_s[c0 + 1];
            float v0 = acc[nt * 4 + 0] + bv0;
            float v1 = acc[nt * 4 + 1] + bv1;
            float v2 = acc[nt * 4 + 2] + bv0;
            float v3 = acc[nt * 4 + 3] + bv1;
            if (mode == 1 || mode == 3) {
                v0 += vr[nt * 4 + 0]; v1 += vr[nt * 4 + 1];
                v2 += vr[nt * 4 + 2]; v3 += vr[nt * 4 + 3];
            }
            if (mode == 2) {
                float2 xl = (row_lo < N) ? *reinterpret_cast<const float2*>(x + (size_t)row_lo * D + c0)
                                         : make_float2(0.f, 0.f);
                float2 xh = (row_hi < N) ? *reinterpret_cast<const float2*>(x + (size_t)row_hi * D + c0)
                                         : make_float2(0.f, 0.f);
                float u0 = u_s[c0], u1 = u_s[c0 + 1];
                v0 += u0 * sspf(xl.x); v1 += u1 * sspf(xl.y);
                v2 += u0 * sspf(xh.x); v3 += u1 * sspf(xh.y);
            }
            if (mode == 1 || mode == 2) {
                vr[nt * 4 + 0] = v0; vr[nt * 4 + 1] = v1;
                vr[nt * 4 + 2] = v2; vr[nt * 4 + 3] = v3;
            }
            float s0 = sspf(v0), s1 = sspf(v1), s2 = sspf(v2), s3 = sspf(v3);
            if (mode == 3) {
                if (row_lo < N)
                    *reinterpret_cast<float2*>(o_out + (size_t)row_lo * D + c0) = make_float2(s0, s1);
                if (row_hi < N)
                    *reinterpret_cast<float2*>(o_out + (size_t)row_hi * D + c0) = make_float2(s2, s3);
            } else {
                int base = (nt >> 1) * 4 + (nt & 1) * 2;
                build_frag(s0, s1, ahi[base], alo[base]);
                build_frag(s2, s3, ahi[base + 1], alo[base + 1]);
            }
        }

        if (storeh) {
            #pragma unroll
            for (int nt = 0; nt < 16; nt++) {
                int c0 = nt * 8 + cb;
                if (row_lo < N)
                    *reinterpret_cast<float2*>(h_out + (size_t)row_lo * D + c0) =
                        make_float2(vr[nt * 4 + 0], vr[nt * 4 + 1]);
                if (row_hi < N)
                    *reinterpret_cast<float2*>(h_out + (size_t)row_hi * D + c0) =
                        make_float2(vr[nt * 4 + 2], vr[nt * 4 + 3]);
            }
        }
        __syncthreads();
    }
}

// ---------------------------------------------------------------------------
// Edge kernel (HMMA gate): one warp processes 16 edges; scatter via red.v4
// after packing 4 columns per even lane with one lane-XOR shuffle.
// ---------------------------------------------------------------------------
__global__ __launch_bounds__(256)
void edge_mma_kernel(const float* __restrict__ g,
                     const int* __restrict__ idx_i,
                     const int* __restrict__ idx_j,
                     const float* __restrict__ mj,
                     float* __restrict__ v,
                     int E, int wg_slot) {
    __shared__ uint32_t wgs[4096];   // Wg frags: hi[2048] + lo[2048]
    {
        const uint4* src = reinterpret_cast<const uint4*>(d_wimg + (size_t)wg_slot * 16384);
        uint4* dst = reinterpret_cast<uint4*>(wgs);
        #pragma unroll
        for (int i = threadIdx.x; i < 1024; i += 256)
            dst[i] = src[i];
    }
    __syncthreads();

    const int t = threadIdx.x, l = t & 31;
    const int gq = l >> 2, m4 = l & 3;
    const int batch = blockIdx.x * 8 + (t >> 5);
    const int e0 = batch * 16;
    if (e0 >= E) return;

    const int r0 = e0 + gq, r1 = r0 + 8;
    const bool v0ok = (r0 < E), v1ok = (r1 < E);
    const int j0 = v0ok ? __ldg(idx_j + r0) : 0;
    const int i0 = v0ok ? __ldg(idx_i + r0) : 0;
    const int j1 = v1ok ? __ldg(idx_j + r1) : 0;
    const int i1 = v1ok ? __ldg(idx_i + r1) : 0;

    // A fragments from g rows (R=32 -> 2 ktiles)
    uint32_t ahi[8], alo[8];
    #pragma unroll
    for (int kt = 0; kt < 2; kt++) {
        int kb = kt * 16 + 2 * m4;
        float2 p00 = v0ok ? *reinterpret_cast<const float2*>(g + (size_t)r0 * 32 + kb)
                          : make_float2(0.f, 0.f);
        float2 p01 = v0ok ? *reinterpret_cast<const float2*>(g + (size_t)r0 * 32 + kb + 8)
                          : make_float2(0.f, 0.f);
        float2 p10 = v1ok ? *reinterpret_cast<const float2*>(g + (size_t)r1 * 32 + kb)
                          : make_float2(0.f, 0.f);
        float2 p11 = v1ok ? *reinterpret_cast<const float2*>(g + (size_t)r1 * 32 + kb + 8)
                          : make_float2(0.f, 0.f);
        build_frag(p00.x, p00.y, ahi[kt * 4 + 0], alo[kt * 4 + 0]);
        build_frag(p10.x, p10.y, ahi[kt * 4 + 1], alo[kt * 4 + 1]);
        build_frag(p01.x, p01.y, ahi[kt * 4 + 2], alo[kt * 4 + 2]);
        build_frag(p11.x, p11.y, ahi[kt * 4 + 3], alo[kt * 4 + 3]);
    }

    float acc[64];
    #pragma unroll
    for (int i = 0; i < 64; i++) acc[i] = 0.0f;

    const char* base = reinterpret_cast<const char*>(wgs);
    const int loff = l * 8;
    #pragma unroll
    for (int nt = 0; nt < 16; nt++) {
        #pragma unroll
        for (int kt = 0; kt < 2; kt++) {
            uint2 bh = *reinterpret_cast<const uint2*>(base + (nt * 2 + kt) * 256 + loff);
            mma_bf16(acc + nt * 4, ahi + kt * 4, bh.x, bh.y);
            mma_bf16(acc + nt * 4, alo + kt * 4, bh.x, bh.y);
            uint2 bl = *reinterpret_cast<const uint2*>(base + 8192 + (nt * 2 + kt) * 256 + loff);
            mma_bf16(acc + nt * 4, ahi + kt * 4, bl.x, bl.y);
        }
    }

    // scatter: v[i,:] += gate * mj[j,:]  (pack 4 cols into even lanes, red.v4)
    const bool evenlane = ((l & 1) == 0);
    #pragma unroll
    for (int nt = 0; nt < 16; nt++) {
        int c0 = nt * 8 + 2 * m4;
        float p0 = 0.f, p1 = 0.f, p2 = 0.f, p3 = 0.f;
        if (v0ok) {
            float2 m0 = *reinterpret_cast<const float2*>(mj + (size_t)j0 * D + c0);
            p0 = acc[nt * 4 + 0] * m0.x;
            p1 = acc[nt * 4 + 1] * m0.y;
        }
        if (v1ok) {
            float2 m1 = *reinterpret_cast<const float2*>(mj + (size_t)j1 * D + c0);
            p2 = acc[nt * 4 + 2] * m1.x;
            p3 = acc[nt * 4 + 3] * m1.y;
        }
        float q0 = __shfl_xor_sync(0xffffffffu, p0, 1);
        float q1 = __shfl_xor_sync(0xffffffffu, p1, 1);
        float q2 = __shfl_xor_sync(0xffffffffu, p2, 1);
        float q3 = __shfl_xor_sync(0xffffffffu, p3, 1);
        if (evenlane) {
            if (v0ok)
                asm volatile("red.global.add.v4.f32 [%0], {%1, %2, %3, %4};"
                             :: "l"(v + (size_t)i0 * D + c0), "f"(p0), "f"(p1), "f"(q0), "f"(q1)
                             : "memory");
            if (v1ok)
                asm volatile("red.global.add.v4.f32 [%0], {%1, %2, %3, %4};"
                             :: "l"(v + (size_t)i1 * D + c0), "f"(p2), "f"(p3), "f"(q2), "f"(q3)
                             : "memory");
        }
    }
}

// ---------------------------------------------------------------------------
// Host-side dispatch
// ---------------------------------------------------------------------------
extern "C" void kernel_launch(void* const* d_in, const int* in_sizes, int n_in,
                              void* d_out, int out_size) {
    const float* x     = (const float*)d_in[0];
    const float* g_ij  = (const float*)d_in[1];
    const float* Wf    = (const float*)d_in[2];
    const float* bf    = (const float*)d_in[3];
    const float* Wg    = (const float*)d_in[4];
    const float* Wj    = (const float*)d_in[5];
    const float* bj    = (const float*)d_in[6];
    const float* Wi    = (const float*)d_in[7];
    const float* bi    = (const float*)d_in[8];
    const float* u     = (const float*)d_in[9];
    const float* rWint = (const float*)d_in[10];
    const float* rbint = (const float*)d_in[11];
    const float* rWatm = (const float*)d_in[12];
    const float* rbatm = (const float*)d_in[13];
    const float* rWout = (const float*)d_in[14];
    const float* rbout = (const float*)d_in[15];
    const int*   idx_i = (const int*)d_in[16];
    const int*   idx_j = (const int*)d_in[17];

    const int N      = in_sizes[0] / D;
    const int E      = in_sizes[16];
    const int n_int  = in_sizes[11] / D;
    const int n_atom = in_sizes[13] / D;
    const int n_out  = in_sizes[15] / D;

    if (N > MAXN) return;
    const int n_mats = 3 + n_int + n_atom + n_out;
    if (n_mats + 1 > MAXMATS) return;

    float *mj, *v;
    cudaGetSymbolAddress((void**)&mj, d_mj);
    cudaGetSymbolAddress((void**)&v,  d_v);

    float* o_out = (float*)d_out;                 // o -> first N*D
    float* h_out = (float*)d_out + (size_t)N * D; // h -> second N*D

    cudaFuncSetAttribute(tc_head_kernel, cudaFuncAttributeMaxDynamicSharedMemorySize, HEAD_SMEM);
    cudaFuncSetAttribute(tc_tail_kernel, cudaFuncAttributeMaxDynamicSharedMemorySize, TAIL_SMEM);

    const int tiles = (N + 127) / 128;

    // 0) split + permute weights (incl. Wg at slot n_mats)
    wsplit_kernel<<<(n_mats + 1) * 8, 256>>>(Wj, Wi, Wf, rWint, rWatm, rWout, Wg,
                                             n_int, n_atom, n_out);

    // 1) mj = ssp(ssp(x)@Wj+bj); v = ssp(ssp(x)@Wi+bi)
    tc_head_kernel<<<tiles, 256, HEAD_SMEM>>>(x, bj, bi, mj, v, N);

    // 2) v += segment_sum( (g_ij @ Wg) * mj[idx_j], idx_i )   [HMMA gate]
    {
        int batches = (E + 15) / 16;
        int blocks  = (batches + 7) / 8;
        edge_mma_kernel<<<blocks, 256>>>(g_ij, idx_i, idx_j, mj, v, E, n_mats);
    }

    // 3) fused register-chained tail with prefetched weights
    tc_tail_kernel<<<tiles, 256, TAIL_SMEM>>>(
        v, x, u, rbint, bf, rbatm, rbout, n_int, n_atom, n_out, h_out, o_out, N);
}